// round 10
// baseline (speedup 1.0000x reference)
#include <cuda_runtime.h>
#include <cuda_bf16.h>
#include <mma.h>
#include <cstddef>

using namespace nvcuda;

// Problem constants
#define N_NODES 50000
#define K_NB    32
#define D_IN    512
#define D_HID   128
#define D_OUT   64

#define M_PAD   50048   // 391 * 128: wmma GEMMs store/load unguarded

// Scratch (device globals: allocation-free, graph-capturable, zero-init)
__device__ float g_h [(size_t)M_PAD * D_HID];   // feat@W1 (no bias)
__device__ float g_h1[(size_t)M_PAD * D_HID];   // relu(median + b1), pad rows stay 0
__device__ float g_g [(size_t)M_PAD * D_OUT];   // h1@W2 (no bias)

// ---------------------------------------------------------------------------
// Generic bf16-split GEMM: C[M,N] = A[M,K] @ B[K,N]
// Terms: hi*hi + hi*lo + lo*hi  (lo*lo dropped, ~2^-16 relative)
// 128-row tile, 256 threads (8 warps, 4x2), BK=32, register-prefetch pipeline.
// MMA issue order is TERM-MAJOR so consecutive HMMAs hit different
// accumulators (reuse distance 2*JF instead of 1) -> no RAW serialization.
// ---------------------------------------------------------------------------
__device__ __forceinline__ void split_bf16(float x, __nv_bfloat16& hi, __nv_bfloat16& lo) {
    hi = __float2bfloat16_rn(x);
    lo = __float2bfloat16_rn(x - __bfloat162float(hi));
}

__device__ __forceinline__ void store_split4(__nv_bfloat16* hi_base, __nv_bfloat16* lo_base,
                                             int off, float4 v) {
    __nv_bfloat16 h0,h1,h2,h3, l0,l1,l2,l3;
    split_bf16(v.x, h0, l0); split_bf16(v.y, h1, l1);
    split_bf16(v.z, h2, l2); split_bf16(v.w, h3, l3);
    *(__nv_bfloat162*)&hi_base[off]     = __nv_bfloat162(h0, h1);
    *(__nv_bfloat162*)&hi_base[off + 2] = __nv_bfloat162(h2, h3);
    *(__nv_bfloat162*)&lo_base[off]     = __nv_bfloat162(l0, l1);
    *(__nv_bfloat162*)&lo_base[off + 2] = __nv_bfloat162(l2, l3);
}

template<int N_DIM, int K_DIM>
__global__ __launch_bounds__(256)
void gemm_bf16s(const float* __restrict__ A, const float* __restrict__ B,
                float* __restrict__ C, int M) {
    constexpr int BK  = 32;
    constexpr int LDA = BK + 8;
    constexpr int LDB = N_DIM + 8;
    constexpr int TPR = N_DIM / 4;
    constexpr int RPP = 256 / TPR;
    constexpr int PB  = BK / RPP;
    constexpr int JF  = N_DIM / 32;
    constexpr int T   = K_DIM / BK;

    __shared__ __nv_bfloat16 As_hi[128 * LDA], As_lo[128 * LDA];
    __shared__ __nv_bfloat16 Bs_hi[BK * LDB],  Bs_lo[BK * LDB];

    const int tid    = threadIdx.x;
    const int wid    = tid >> 5;
    const int warp_m = wid >> 1;
    const int warp_n = wid & 1;
    const int row0   = blockIdx.x * 128;

    const int ar  = tid >> 3;
    const int ac4 = (tid & 7) * 4;
    const int br  = tid / TPR;
    const int bc4 = (tid % TPR) * 4;

    wmma::fragment<wmma::accumulator, 16, 16, 16, float> acc[2][JF];
#pragma unroll
    for (int i = 0; i < 2; ++i)
#pragma unroll
        for (int j = 0; j < JF; ++j) wmma::fill_fragment(acc[i][j], 0.0f);

    float4 pa[4], pb[PB];

#pragma unroll
    for (int p = 0; p < 4; ++p) {
        int row = ar + p * 32;
        pa[p] = make_float4(0.f, 0.f, 0.f, 0.f);
        if (row0 + row < M)
            pa[p] = *(const float4*)&A[(size_t)(row0 + row) * K_DIM + ac4];
    }
#pragma unroll
    for (int p = 0; p < PB; ++p)
        pb[p] = *(const float4*)&B[(size_t)(br + p * RPP) * N_DIM + bc4];

    for (int t = 0; t < T; ++t) {
#pragma unroll
        for (int p = 0; p < 4; ++p)
            store_split4(As_hi, As_lo, (ar + p * 32) * LDA + ac4, pa[p]);
#pragma unroll
        for (int p = 0; p < PB; ++p)
            store_split4(Bs_hi, Bs_lo, (br + p * RPP) * LDB + bc4, pb[p]);
        __syncthreads();

        if (t + 1 < T) {
            int k0 = (t + 1) * BK;
#pragma unroll
            for (int p = 0; p < 4; ++p) {
                int row = ar + p * 32;
                pa[p] = make_float4(0.f, 0.f, 0.f, 0.f);
                if (row0 + row < M)
                    pa[p] = *(const float4*)&A[(size_t)(row0 + row) * K_DIM + k0 + ac4];
            }
#pragma unroll
            for (int p = 0; p < PB; ++p)
                pb[p] = *(const float4*)&B[(size_t)(k0 + br + p * RPP) * N_DIM + bc4];
        }

#pragma unroll
        for (int kk = 0; kk < 2; ++kk) {
            wmma::fragment<wmma::matrix_b, 16, 16, 16,
                           __nv_bfloat16, wmma::row_major> bh[JF], bl[JF];
#pragma unroll
            for (int j = 0; j < JF; ++j) {
                wmma::load_matrix_sync(bh[j], &Bs_hi[(kk * 16) * LDB + warp_n * (N_DIM / 2) + j * 16], LDB);
                wmma::load_matrix_sync(bl[j], &Bs_lo[(kk * 16) * LDB + warp_n * (N_DIM / 2) + j * 16], LDB);
            }
            wmma::fragment<wmma::matrix_a, 16, 16, 16,
                           __nv_bfloat16, wmma::row_major> ah[2], al[2];
#pragma unroll
            for (int i = 0; i < 2; ++i) {
                wmma::load_matrix_sync(ah[i], &As_hi[(warp_m * 32 + i * 16) * LDA + kk * 16], LDA);
                wmma::load_matrix_sync(al[i], &As_lo[(warp_m * 32 + i * 16) * LDA + kk * 16], LDA);
            }
            // Term-major: consecutive MMAs target different accumulators.
#pragma unroll
            for (int i = 0; i < 2; ++i)
#pragma unroll
                for (int j = 0; j < JF; ++j)
                    wmma::mma_sync(acc[i][j], ah[i], bh[j], acc[i][j]);
#pragma unroll
            for (int i = 0; i < 2; ++i)
#pragma unroll
                for (int j = 0; j < JF; ++j)
                    wmma::mma_sync(acc[i][j], ah[i], bl[j], acc[i][j]);
#pragma unroll
            for (int i = 0; i < 2; ++i)
#pragma unroll
                for (int j = 0; j < JF; ++j)
                    wmma::mma_sync(acc[i][j], al[i], bh[j], acc[i][j]);
        }
        __syncthreads();
    }

#pragma unroll
    for (int i = 0; i < 2; ++i)
#pragma unroll
        for (int j = 0; j < JF; ++j) {
            int r = row0 + warp_m * 32 + i * 16;
            int c = warp_n * (N_DIM / 2) + j * 16;
            wmma::store_matrix_sync(&C[(size_t)r * N_DIM + c], acc[i][j],
                                    N_DIM, wmma::mem_row_major);
        }
}

// ---------------------------------------------------------------------------
// Batcher odd-even merge sort on float2 lanes, dual-pipe comparators.
// ---------------------------------------------------------------------------
template<int I, int J>
__device__ __forceinline__ void cmpswap2(float2* v) {
    constexpr bool USE_FMA = (((I * 37 + J * 11) % 19) < 6);
    if constexpr (USE_FMA) {
        float sx = v[I].x + v[J].x, dx = v[I].x - v[J].x;
        float sy = v[I].y + v[J].y, dy = v[I].y - v[J].y;
        float lx = (sx - fabsf(dx)) * 0.5f;
        float ly = (sy - fabsf(dy)) * 0.5f;
        v[I].x = lx; v[J].x = sx - lx;
        v[I].y = ly; v[J].y = sy - ly;
    } else {
        float ax = v[I].x, bx = v[J].x;
        float ay = v[I].y, by = v[J].y;
        v[I].x = fminf(ax, bx); v[J].x = fmaxf(ax, bx);
        v[I].y = fminf(ay, by); v[J].y = fmaxf(ay, by);
    }
}

template<int I, int END, int STEP, int R>
__device__ __forceinline__ void oem_cloop(float2* v) {
    if constexpr (I + R < END) {
        cmpswap2<I, I + R>(v);
        oem_cloop<I + STEP, END, STEP, R>(v);
    }
}

template<int LO, int N, int R>
__device__ __forceinline__ void oem_merge(float2* v) {
    constexpr int M = R * 2;
    if constexpr (M < N) {
        oem_merge<LO, N, M>(v);
        oem_merge<LO + R, N, M>(v);
        oem_cloop<LO + R, LO + N, M, R>(v);
    } else {
        cmpswap2<LO, LO + R>(v);
    }
}

template<int LO, int N>
__device__ __forceinline__ void oem_sort(float2* v) {
    if constexpr (N > 1) {
        constexpr int M = N / 2;
        oem_sort<LO, M>(v);
        oem_sort<LO + M, M>(v);
        oem_merge<LO, N, 1>(v);
    }
}

// Lower median (rank 15) of 32, on both float2 lanes.
__device__ __forceinline__ float2 median32_f2(float2* v) {
    oem_sort<0, 16>(v);
    oem_sort<0, 16>(v + 16);
    float mx = fminf(v[0].x, v[31].x);
    float my = fminf(v[0].y, v[31].y);
#pragma unroll
    for (int i = 1; i < 16; ++i) {
        mx = fmaxf(mx, fminf(v[i].x, v[31 - i].x));
        my = fmaxf(my, fminf(v[i].y, v[31 - i].y));
    }
    return make_float2(mx, my);
}

// ---------------------------------------------------------------------------
// Layer-1 median + bias + ReLU: 2 nodes/block, 64 threads/node, 2 feat/thread.
// ---------------------------------------------------------------------------
__global__ __launch_bounds__(128)
void median_relu_f2(const int* __restrict__ nb, const float* __restrict__ bias) {
    const int local = threadIdx.x >> 6;
    const int n  = blockIdx.x * 2 + local;
    const int d2 = threadIdx.x & 63;

    __shared__ int sidx[2 * K_NB];
    if (threadIdx.x < 2 * K_NB)
        sidx[threadIdx.x] = nb[(size_t)(blockIdx.x * 2) * K_NB + threadIdx.x];
    __syncthreads();

    const float2* hp = (const float2*)g_h;
    float2 v[K_NB];
#pragma unroll
    for (int k = 0; k < K_NB; ++k)
        v[k] = __ldg(&hp[(size_t)sidx[local * K_NB + k] * (D_HID / 2) + d2]);

    float2 med = median32_f2(v);
    float2 b = ((const float2*)bias)[d2];
    float2 r = make_float2(fmaxf(med.x + b.x, 0.0f), fmaxf(med.y + b.y, 0.0f));
    ((float2*)g_h1)[(size_t)n * (D_HID / 2) + d2] = r;
}

// ---------------------------------------------------------------------------
// Layer-2 median + bias: 4 nodes/block, 32 threads/node, 2 feat/thread.
// ---------------------------------------------------------------------------
__global__ __launch_bounds__(128)
void median_f2_out(const int* __restrict__ nb, const float* __restrict__ bias,
                   float* __restrict__ out) {
    const int local = threadIdx.x >> 5;
    const int n  = blockIdx.x * 4 + local;
    const int d2 = threadIdx.x & 31;

    __shared__ int sidx[4 * K_NB];
    if (threadIdx.x < 4 * K_NB)
        sidx[threadIdx.x] = nb[(size_t)(blockIdx.x * 4) * K_NB + threadIdx.x];
    __syncthreads();

    const float2* gp = (const float2*)g_g;
    float2 v[K_NB];
#pragma unroll
    for (int k = 0; k < K_NB; ++k)
        v[k] = __ldg(&gp[(size_t)sidx[local * K_NB + k] * (D_OUT / 2) + d2]);

    float2 med = median32_f2(v);
    float2 b = ((const float2*)bias)[d2];
    ((float2*)out)[(size_t)n * (D_OUT / 2) + d2] =
        make_float2(med.x + b.x, med.y + b.y);
}

// ---------------------------------------------------------------------------
extern "C" void kernel_launch(void* const* d_in, const int* in_sizes, int n_in,
                              void* d_out, int out_size) {
    const float* feat = (const float*)d_in[0];
    const float* W1   = (const float*)d_in[1];
    const float* b1   = (const float*)d_in[2];
    const float* W2   = (const float*)d_in[3];
    const float* b2   = (const float*)d_in[4];
    const int*   nb   = (const int*)d_in[5];
    float* out = (float*)d_out;

    void *ph = nullptr, *ph1 = nullptr, *pg = nullptr;
    cudaGetSymbolAddress(&ph,  g_h);
    cudaGetSymbolAddress(&ph1, g_h1);
    cudaGetSymbolAddress(&pg,  g_g);
    float* h  = (float*)ph;
    float* h1 = (float*)ph1;
    float* g  = (float*)pg;

    // 1) h = feat @ W1   [50000,512]x[512,128]  (bf16-split wmma)
    gemm_bf16s<D_HID, D_IN><<<M_PAD / 128, 256>>>(feat, W1, h, N_NODES);

    // 2) h1 = relu(median_k h[nb] + b1)
    median_relu_f2<<<N_NODES / 2, 128>>>(nb, b1);

    // 3) g = h1 @ W2   [50048,128]x[128,64]  (bf16-split wmma, pad rows are 0)
    gemm_bf16s<D_OUT, D_HID><<<M_PAD / 128, 256>>>(h1, W2, g, M_PAD);

    // 4) out = median_k g[nb] + b2
    median_f2_out<<<N_NODES / 4, 128>>>(nb, b2, out);
}

// round 13
// speedup vs baseline: 1.0480x; 1.0480x over previous
#include <cuda_runtime.h>
#include <cuda_bf16.h>
#include <mma.h>
#include <cstddef>

using namespace nvcuda;

// Problem constants
#define N_NODES 50000
#define K_NB    32
#define D_IN    512
#define D_HID   128
#define D_OUT   64

#define M_PAD   50048   // 391 * 128: wmma GEMMs store/load unguarded

// Scratch (device globals: allocation-free, graph-capturable, zero-init)
__device__ float g_h [(size_t)M_PAD * D_HID];   // feat@W1 (no bias)
__device__ float g_h1[(size_t)M_PAD * D_HID];   // relu(median + b1), pad rows stay 0
__device__ float g_g [(size_t)M_PAD * D_OUT];   // h1@W2 (no bias)

// ---------------------------------------------------------------------------
// Generic bf16-split GEMM: C[M,N] = A[M,K] @ B[K,N]
// Terms: hi*hi + hi*lo + lo*hi  (lo*lo dropped, ~2^-16 relative)
// Block tile 128x64, 256 threads (8 warps, 4x2; 32x32 per warp), BK=32,
// register-prefetch pipeline, __launch_bounds__(256,2) -> 2 CTAs/SM so
// barrier + load-tail stalls of one CTA are covered by the other.
// Grid: (N_DIM/64 col-blocks, M/128 row-blocks); col-blocks adjacent -> A
// rows are fetched once into L2 and reused by the sibling CTA.
// ---------------------------------------------------------------------------
__device__ __forceinline__ void split_bf16(float x, __nv_bfloat16& hi, __nv_bfloat16& lo) {
    hi = __float2bfloat16_rn(x);
    lo = __float2bfloat16_rn(x - __bfloat162float(hi));
}

__device__ __forceinline__ void store_split4(__nv_bfloat16* hi_base, __nv_bfloat16* lo_base,
                                             int off, float4 v) {
    __nv_bfloat16 h0,h1,h2,h3, l0,l1,l2,l3;
    split_bf16(v.x, h0, l0); split_bf16(v.y, h1, l1);
    split_bf16(v.z, h2, l2); split_bf16(v.w, h3, l3);
    *(__nv_bfloat162*)&hi_base[off]     = __nv_bfloat162(h0, h1);
    *(__nv_bfloat162*)&hi_base[off + 2] = __nv_bfloat162(h2, h3);
    *(__nv_bfloat162*)&lo_base[off]     = __nv_bfloat162(l0, l1);
    *(__nv_bfloat162*)&lo_base[off + 2] = __nv_bfloat162(l2, l3);
}

template<int N_DIM, int K_DIM>
__global__ __launch_bounds__(256, 2)
void gemm_bf16s(const float* __restrict__ A, const float* __restrict__ B,
                float* __restrict__ C, int M) {
    constexpr int BK  = 32;
    constexpr int LDA = BK + 8;        // 40 bf16 row stride
    constexpr int LDB = 64 + 8;        // 72 bf16 row stride (64-col tile)
    constexpr int T   = K_DIM / BK;    // k-tiles

    __shared__ __nv_bfloat16 As_hi[128 * LDA], As_lo[128 * LDA];
    __shared__ __nv_bfloat16 Bs_hi[BK * LDB],  Bs_lo[BK * LDB];

    const int tid    = threadIdx.x;
    const int wid    = tid >> 5;
    const int warp_m = wid >> 1;            // 0..3 -> 32-row strip
    const int warp_n = wid & 1;             // 0..1 -> 32-col strip
    const int row0   = blockIdx.y * 128;
    const int col0   = blockIdx.x * 64;

    const int ar  = tid >> 3;               // A: 8 thr/row, rows ar + p*32
    const int ac4 = (tid & 7) * 4;
    const int br  = tid >> 4;               // B: 16 thr/row, rows br + p*16
    const int bc4 = (tid & 15) * 4;

    wmma::fragment<wmma::accumulator, 16, 16, 16, float> acc[2][2];
#pragma unroll
    for (int i = 0; i < 2; ++i)
#pragma unroll
        for (int j = 0; j < 2; ++j) wmma::fill_fragment(acc[i][j], 0.0f);

    float4 pa[4], pb[2];

    // Prologue: load k-tile 0 into registers
#pragma unroll
    for (int p = 0; p < 4; ++p) {
        int row = ar + p * 32;
        pa[p] = make_float4(0.f, 0.f, 0.f, 0.f);
        if (row0 + row < M)
            pa[p] = *(const float4*)&A[(size_t)(row0 + row) * K_DIM + ac4];
    }
#pragma unroll
    for (int p = 0; p < 2; ++p)
        pb[p] = *(const float4*)&B[(size_t)(br + p * 16) * N_DIM + col0 + bc4];

    for (int t = 0; t < T; ++t) {
        // Store prefetched tile to smem (fp32 -> bf16 hi/lo)
#pragma unroll
        for (int p = 0; p < 4; ++p)
            store_split4(As_hi, As_lo, (ar + p * 32) * LDA + ac4, pa[p]);
#pragma unroll
        for (int p = 0; p < 2; ++p)
            store_split4(Bs_hi, Bs_lo, (br + p * 16) * LDB + bc4, pb[p]);
        __syncthreads();

        // Prefetch next tile (hidden behind MMA compute / sibling CTA)
        if (t + 1 < T) {
            int k0 = (t + 1) * BK;
#pragma unroll
            for (int p = 0; p < 4; ++p) {
                int row = ar + p * 32;
                pa[p] = make_float4(0.f, 0.f, 0.f, 0.f);
                if (row0 + row < M)
                    pa[p] = *(const float4*)&A[(size_t)(row0 + row) * K_DIM + k0 + ac4];
            }
#pragma unroll
            for (int p = 0; p < 2; ++p)
                pb[p] = *(const float4*)&B[(size_t)(k0 + br + p * 16) * N_DIM + col0 + bc4];
        }

        // Compute on current smem tile
#pragma unroll
        for (int kk = 0; kk < 2; ++kk) {
            wmma::fragment<wmma::matrix_b, 16, 16, 16,
                           __nv_bfloat16, wmma::row_major> bh[2], bl[2];
#pragma unroll
            for (int j = 0; j < 2; ++j) {
                wmma::load_matrix_sync(bh[j], &Bs_hi[(kk * 16) * LDB + warp_n * 32 + j * 16], LDB);
                wmma::load_matrix_sync(bl[j], &Bs_lo[(kk * 16) * LDB + warp_n * 32 + j * 16], LDB);
            }
#pragma unroll
            for (int i = 0; i < 2; ++i) {
                wmma::fragment<wmma::matrix_a, 16, 16, 16,
                               __nv_bfloat16, wmma::row_major> ah, al;
                wmma::load_matrix_sync(ah, &As_hi[(warp_m * 32 + i * 16) * LDA + kk * 16], LDA);
                wmma::load_matrix_sync(al, &As_lo[(warp_m * 32 + i * 16) * LDA + kk * 16], LDA);
#pragma unroll
                for (int j = 0; j < 2; ++j) {
                    wmma::mma_sync(acc[i][j], ah, bh[j], acc[i][j]);
                    wmma::mma_sync(acc[i][j], ah, bl[j], acc[i][j]);
                    wmma::mma_sync(acc[i][j], al, bh[j], acc[i][j]);
                }
            }
        }
        __syncthreads();
    }

    // Store (C padded to M_PAD rows -> unguarded)
#pragma unroll
    for (int i = 0; i < 2; ++i)
#pragma unroll
        for (int j = 0; j < 2; ++j) {
            int r = row0 + warp_m * 32 + i * 16;
            int c = col0 + warp_n * 32 + j * 16;
            wmma::store_matrix_sync(&C[(size_t)r * N_DIM + c], acc[i][j],
                                    N_DIM, wmma::mem_row_major);
        }
}

// ---------------------------------------------------------------------------
// Batcher odd-even merge sort on float2 lanes, dual-pipe comparators.
// ---------------------------------------------------------------------------
template<int I, int J>
__device__ __forceinline__ void cmpswap2(float2* v) {
    constexpr bool USE_FMA = (((I * 37 + J * 11) % 19) < 6);
    if constexpr (USE_FMA) {
        float sx = v[I].x + v[J].x, dx = v[I].x - v[J].x;
        float sy = v[I].y + v[J].y, dy = v[I].y - v[J].y;
        float lx = (sx - fabsf(dx)) * 0.5f;
        float ly = (sy - fabsf(dy)) * 0.5f;
        v[I].x = lx; v[J].x = sx - lx;
        v[I].y = ly; v[J].y = sy - ly;
    } else {
        float ax = v[I].x, bx = v[J].x;
        float ay = v[I].y, by = v[J].y;
        v[I].x = fminf(ax, bx); v[J].x = fmaxf(ax, bx);
        v[I].y = fminf(ay, by); v[J].y = fmaxf(ay, by);
    }
}

template<int I, int END, int STEP, int R>
__device__ __forceinline__ void oem_cloop(float2* v) {
    if constexpr (I + R < END) {
        cmpswap2<I, I + R>(v);
        oem_cloop<I + STEP, END, STEP, R>(v);
    }
}

template<int LO, int N, int R>
__device__ __forceinline__ void oem_merge(float2* v) {
    constexpr int M = R * 2;
    if constexpr (M < N) {
        oem_merge<LO, N, M>(v);
        oem_merge<LO + R, N, M>(v);
        oem_cloop<LO + R, LO + N, M, R>(v);
    } else {
        cmpswap2<LO, LO + R>(v);
    }
}

template<int LO, int N>
__device__ __forceinline__ void oem_sort(float2* v) {
    if constexpr (N > 1) {
        constexpr int M = N / 2;
        oem_sort<LO, M>(v);
        oem_sort<LO + M, M>(v);
        oem_merge<LO, N, 1>(v);
    }
}

// Lower median (rank 15) of 32, on both float2 lanes.
__device__ __forceinline__ float2 median32_f2(float2* v) {
    oem_sort<0, 16>(v);
    oem_sort<0, 16>(v + 16);
    float mx = fminf(v[0].x, v[31].x);
    float my = fminf(v[0].y, v[31].y);
#pragma unroll
    for (int i = 1; i < 16; ++i) {
        mx = fmaxf(mx, fminf(v[i].x, v[31 - i].x));
        my = fmaxf(my, fminf(v[i].y, v[31 - i].y));
    }
    return make_float2(mx, my);
}

// ---------------------------------------------------------------------------
// Layer-1 median + bias + ReLU: 2 nodes/block, 64 threads/node, 2 feat/thread.
// ---------------------------------------------------------------------------
__global__ __launch_bounds__(128)
void median_relu_f2(const int* __restrict__ nb, const float* __restrict__ bias) {
    const int local = threadIdx.x >> 6;
    const int n  = blockIdx.x * 2 + local;
    const int d2 = threadIdx.x & 63;

    __shared__ int sidx[2 * K_NB];
    if (threadIdx.x < 2 * K_NB)
        sidx[threadIdx.x] = nb[(size_t)(blockIdx.x * 2) * K_NB + threadIdx.x];
    __syncthreads();

    const float2* hp = (const float2*)g_h;
    float2 v[K_NB];
#pragma unroll
    for (int k = 0; k < K_NB; ++k)
        v[k] = __ldg(&hp[(size_t)sidx[local * K_NB + k] * (D_HID / 2) + d2]);

    float2 med = median32_f2(v);
    float2 b = ((const float2*)bias)[d2];
    float2 r = make_float2(fmaxf(med.x + b.x, 0.0f), fmaxf(med.y + b.y, 0.0f));
    ((float2*)g_h1)[(size_t)n * (D_HID / 2) + d2] = r;
}

// ---------------------------------------------------------------------------
// Layer-2 median + bias: 4 nodes/block, 32 threads/node, 2 feat/thread.
// ---------------------------------------------------------------------------
__global__ __launch_bounds__(128)
void median_f2_out(const int* __restrict__ nb, const float* __restrict__ bias,
                   float* __restrict__ out) {
    const int local = threadIdx.x >> 5;
    const int n  = blockIdx.x * 4 + local;
    const int d2 = threadIdx.x & 31;

    __shared__ int sidx[4 * K_NB];
    if (threadIdx.x < 4 * K_NB)
        sidx[threadIdx.x] = nb[(size_t)(blockIdx.x * 4) * K_NB + threadIdx.x];
    __syncthreads();

    const float2* gp = (const float2*)g_g;
    float2 v[K_NB];
#pragma unroll
    for (int k = 0; k < K_NB; ++k)
        v[k] = __ldg(&gp[(size_t)sidx[local * K_NB + k] * (D_OUT / 2) + d2]);

    float2 med = median32_f2(v);
    float2 b = ((const float2*)bias)[d2];
    ((float2*)out)[(size_t)n * (D_OUT / 2) + d2] =
        make_float2(med.x + b.x, med.y + b.y);
}

// ---------------------------------------------------------------------------
extern "C" void kernel_launch(void* const* d_in, const int* in_sizes, int n_in,
                              void* d_out, int out_size) {
    const float* feat = (const float*)d_in[0];
    const float* W1   = (const float*)d_in[1];
    const float* b1   = (const float*)d_in[2];
    const float* W2   = (const float*)d_in[3];
    const float* b2   = (const float*)d_in[4];
    const int*   nb   = (const int*)d_in[5];
    float* out = (float*)d_out;

    void *ph = nullptr, *ph1 = nullptr, *pg = nullptr;
    cudaGetSymbolAddress(&ph,  g_h);
    cudaGetSymbolAddress(&ph1, g_h1);
    cudaGetSymbolAddress(&pg,  g_g);
    float* h  = (float*)ph;
    float* h1 = (float*)ph1;
    float* g  = (float*)pg;

    // 1) h = feat @ W1   [50000,512]x[512,128]  (bf16-split wmma, 2 CTA/SM)
    {
        dim3 grid(D_HID / 64, M_PAD / 128);   // (2, 391), col-blocks adjacent
        gemm_bf16s<D_HID, D_IN><<<grid, 256>>>(feat, W1, h, N_NODES);
    }

    // 2) h1 = relu(median_k h[nb] + b1)
    median_relu_f2<<<N_NODES / 2, 128>>>(nb, b1);

    // 3) g = h1 @ W2   [50048,128]x[128,64]  (bf16-split wmma, pad rows are 0)
    {
        dim3 grid(D_OUT / 64, M_PAD / 128);   // (1, 391)
        gemm_bf16s<D_OUT, D_HID><<<grid, 256>>>(h1, W2, g, M_PAD);
    }

    // 4) out = median_k g[nb] + b2
    median_f2_out<<<N_NODES / 4, 128>>>(nb, b2, out);
}

// round 14
// speedup vs baseline: 1.1600x; 1.1068x over previous
#include <cuda_runtime.h>
#include <cuda_bf16.h>
#include <mma.h>
#include <cstddef>

using namespace nvcuda;

// Problem constants
#define N_NODES 50000
#define K_NB    32
#define D_IN    512
#define D_HID   128
#define D_OUT   64

#define M_PAD   50048   // 391 * 128: wmma GEMMs store/load unguarded

// Scratch (device globals: allocation-free, graph-capturable, zero-init)
__device__ float g_h [(size_t)M_PAD * D_HID];   // feat@W1 (no bias)
__device__ float g_h1[(size_t)M_PAD * D_HID];   // relu(median + b1), pad rows stay 0
__device__ float g_g [(size_t)M_PAD * D_OUT];   // h1@W2 (no bias)

// ---------------------------------------------------------------------------
// Generic bf16-split GEMM: C[M,N] = A[M,K] @ B[K,N]
// Terms: hi*hi + hi*lo + lo*hi  (lo*lo dropped, ~2^-16 relative)
// Block tile 128x64, 256 threads (8 warps, 4x2; 32x32 per warp), BK=32,
// register-prefetch pipeline, 2 CTAs/SM (validated win in R13).
// ---------------------------------------------------------------------------
__device__ __forceinline__ void split_bf16(float x, __nv_bfloat16& hi, __nv_bfloat16& lo) {
    hi = __float2bfloat16_rn(x);
    lo = __float2bfloat16_rn(x - __bfloat162float(hi));
}

__device__ __forceinline__ void store_split4(__nv_bfloat16* hi_base, __nv_bfloat16* lo_base,
                                             int off, float4 v) {
    __nv_bfloat16 h0,h1,h2,h3, l0,l1,l2,l3;
    split_bf16(v.x, h0, l0); split_bf16(v.y, h1, l1);
    split_bf16(v.z, h2, l2); split_bf16(v.w, h3, l3);
    *(__nv_bfloat162*)&hi_base[off]     = __nv_bfloat162(h0, h1);
    *(__nv_bfloat162*)&hi_base[off + 2] = __nv_bfloat162(h2, h3);
    *(__nv_bfloat162*)&lo_base[off]     = __nv_bfloat162(l0, l1);
    *(__nv_bfloat162*)&lo_base[off + 2] = __nv_bfloat162(l2, l3);
}

template<int N_DIM, int K_DIM>
__global__ __launch_bounds__(256, 2)
void gemm_bf16s(const float* __restrict__ A, const float* __restrict__ B,
                float* __restrict__ C, int M) {
    constexpr int BK  = 32;
    constexpr int LDA = BK + 8;
    constexpr int LDB = 64 + 8;
    constexpr int T   = K_DIM / BK;

    __shared__ __nv_bfloat16 As_hi[128 * LDA], As_lo[128 * LDA];
    __shared__ __nv_bfloat16 Bs_hi[BK * LDB],  Bs_lo[BK * LDB];

    const int tid    = threadIdx.x;
    const int wid    = tid >> 5;
    const int warp_m = wid >> 1;
    const int warp_n = wid & 1;
    const int row0   = blockIdx.y * 128;
    const int col0   = blockIdx.x * 64;

    const int ar  = tid >> 3;
    const int ac4 = (tid & 7) * 4;
    const int br  = tid >> 4;
    const int bc4 = (tid & 15) * 4;

    wmma::fragment<wmma::accumulator, 16, 16, 16, float> acc[2][2];
#pragma unroll
    for (int i = 0; i < 2; ++i)
#pragma unroll
        for (int j = 0; j < 2; ++j) wmma::fill_fragment(acc[i][j], 0.0f);

    float4 pa[4], pb[2];

#pragma unroll
    for (int p = 0; p < 4; ++p) {
        int row = ar + p * 32;
        pa[p] = make_float4(0.f, 0.f, 0.f, 0.f);
        if (row0 + row < M)
            pa[p] = *(const float4*)&A[(size_t)(row0 + row) * K_DIM + ac4];
    }
#pragma unroll
    for (int p = 0; p < 2; ++p)
        pb[p] = *(const float4*)&B[(size_t)(br + p * 16) * N_DIM + col0 + bc4];

    for (int t = 0; t < T; ++t) {
#pragma unroll
        for (int p = 0; p < 4; ++p)
            store_split4(As_hi, As_lo, (ar + p * 32) * LDA + ac4, pa[p]);
#pragma unroll
        for (int p = 0; p < 2; ++p)
            store_split4(Bs_hi, Bs_lo, (br + p * 16) * LDB + bc4, pb[p]);
        __syncthreads();

        if (t + 1 < T) {
            int k0 = (t + 1) * BK;
#pragma unroll
            for (int p = 0; p < 4; ++p) {
                int row = ar + p * 32;
                pa[p] = make_float4(0.f, 0.f, 0.f, 0.f);
                if (row0 + row < M)
                    pa[p] = *(const float4*)&A[(size_t)(row0 + row) * K_DIM + k0 + ac4];
            }
#pragma unroll
            for (int p = 0; p < 2; ++p)
                pb[p] = *(const float4*)&B[(size_t)(k0 + br + p * 16) * N_DIM + col0 + bc4];
        }

#pragma unroll
        for (int kk = 0; kk < 2; ++kk) {
            wmma::fragment<wmma::matrix_b, 16, 16, 16,
                           __nv_bfloat16, wmma::row_major> bh[2], bl[2];
#pragma unroll
            for (int j = 0; j < 2; ++j) {
                wmma::load_matrix_sync(bh[j], &Bs_hi[(kk * 16) * LDB + warp_n * 32 + j * 16], LDB);
                wmma::load_matrix_sync(bl[j], &Bs_lo[(kk * 16) * LDB + warp_n * 32 + j * 16], LDB);
            }
#pragma unroll
            for (int i = 0; i < 2; ++i) {
                wmma::fragment<wmma::matrix_a, 16, 16, 16,
                               __nv_bfloat16, wmma::row_major> ah, al;
                wmma::load_matrix_sync(ah, &As_hi[(warp_m * 32 + i * 16) * LDA + kk * 16], LDA);
                wmma::load_matrix_sync(al, &As_lo[(warp_m * 32 + i * 16) * LDA + kk * 16], LDA);
#pragma unroll
                for (int j = 0; j < 2; ++j) {
                    wmma::mma_sync(acc[i][j], ah, bh[j], acc[i][j]);
                    wmma::mma_sync(acc[i][j], ah, bl[j], acc[i][j]);
                    wmma::mma_sync(acc[i][j], al, bh[j], acc[i][j]);
                }
            }
        }
        __syncthreads();
    }

#pragma unroll
    for (int i = 0; i < 2; ++i)
#pragma unroll
        for (int j = 0; j < 2; ++j) {
            int r = row0 + warp_m * 32 + i * 16;
            int c = col0 + warp_n * 32 + j * 16;
            wmma::store_matrix_sync(&C[(size_t)r * N_DIM + c], acc[i][j],
                                    N_DIM, wmma::mem_row_major);
        }
}

// ---------------------------------------------------------------------------
// Batcher odd-even merge sort on float4 lanes (4 independent medians/thread),
// dual-pipe comparators (~6/19 FMA-pipe form) for alu/fma issue balance.
// ---------------------------------------------------------------------------
template<int I, int J>
__device__ __forceinline__ void cmpswap4(float4* v) {
    constexpr bool USE_FMA = (((I * 37 + J * 11) % 19) < 6);
    if constexpr (USE_FMA) {
        float sx = v[I].x + v[J].x, dx = v[I].x - v[J].x;
        float sy = v[I].y + v[J].y, dy = v[I].y - v[J].y;
        float sz = v[I].z + v[J].z, dz = v[I].z - v[J].z;
        float sw = v[I].w + v[J].w, dw = v[I].w - v[J].w;
        float lx = (sx - fabsf(dx)) * 0.5f;
        float ly = (sy - fabsf(dy)) * 0.5f;
        float lz = (sz - fabsf(dz)) * 0.5f;
        float lw = (sw - fabsf(dw)) * 0.5f;
        v[I].x = lx; v[J].x = sx - lx;
        v[I].y = ly; v[J].y = sy - ly;
        v[I].z = lz; v[J].z = sz - lz;
        v[I].w = lw; v[J].w = sw - lw;
    } else {
        float ax = v[I].x, bx = v[J].x;
        float ay = v[I].y, by = v[J].y;
        float az = v[I].z, bz = v[J].z;
        float aw = v[I].w, bw = v[J].w;
        v[I].x = fminf(ax, bx); v[J].x = fmaxf(ax, bx);
        v[I].y = fminf(ay, by); v[J].y = fmaxf(ay, by);
        v[I].z = fminf(az, bz); v[J].z = fmaxf(az, bz);
        v[I].w = fminf(aw, bw); v[J].w = fmaxf(aw, bw);
    }
}

template<int I, int END, int STEP, int R>
__device__ __forceinline__ void oem_cloop(float4* v) {
    if constexpr (I + R < END) {
        cmpswap4<I, I + R>(v);
        oem_cloop<I + STEP, END, STEP, R>(v);
    }
}

template<int LO, int N, int R>
__device__ __forceinline__ void oem_merge(float4* v) {
    constexpr int M = R * 2;
    if constexpr (M < N) {
        oem_merge<LO, N, M>(v);
        oem_merge<LO + R, N, M>(v);
        oem_cloop<LO + R, LO + N, M, R>(v);
    } else {
        cmpswap4<LO, LO + R>(v);
    }
}

template<int LO, int N>
__device__ __forceinline__ void oem_sort(float4* v) {
    if constexpr (N > 1) {
        constexpr int M = N / 2;
        oem_sort<LO, M>(v);
        oem_sort<LO + M, M>(v);
        oem_merge<LO, N, 1>(v);
    }
}

// Lower median (rank 15) of 32 on all four float4 lanes.
__device__ __forceinline__ float4 median32_f4(float4* v) {
    oem_sort<0, 16>(v);
    oem_sort<0, 16>(v + 16);
    float mx = fminf(v[0].x, v[31].x);
    float my = fminf(v[0].y, v[31].y);
    float mz = fminf(v[0].z, v[31].z);
    float mw = fminf(v[0].w, v[31].w);
#pragma unroll
    for (int i = 1; i < 16; ++i) {
        mx = fmaxf(mx, fminf(v[i].x, v[31 - i].x));
        my = fmaxf(my, fminf(v[i].y, v[31 - i].y));
        mz = fmaxf(mz, fminf(v[i].z, v[31 - i].z));
        mw = fmaxf(mw, fminf(v[i].w, v[31 - i].w));
    }
    return make_float4(mx, my, mz, mw);
}

// ---------------------------------------------------------------------------
// Layer-1 median + bias + ReLU: 4 nodes/block, 32 threads/node, 4 feat/thread.
// ---------------------------------------------------------------------------
__global__ __launch_bounds__(128, 1)
void median_relu_f4(const int* __restrict__ nb, const float* __restrict__ bias) {
    const int local = threadIdx.x >> 5;               // 0..3
    const int n  = blockIdx.x * 4 + local;
    const int d4 = threadIdx.x & 31;                  // float4 feature index

    __shared__ int sidx[4 * K_NB];
    if (threadIdx.x < 4 * K_NB)
        sidx[threadIdx.x] = nb[(size_t)(blockIdx.x * 4) * K_NB + threadIdx.x];
    __syncthreads();

    const float4* hp = (const float4*)g_h;
    float4 v[K_NB];
#pragma unroll
    for (int k = 0; k < K_NB; ++k)
        v[k] = __ldg(&hp[(size_t)sidx[local * K_NB + k] * (D_HID / 4) + d4]);

    float4 med = median32_f4(v);
    float4 b = ((const float4*)bias)[d4];
    float4 r = make_float4(fmaxf(med.x + b.x, 0.0f), fmaxf(med.y + b.y, 0.0f),
                           fmaxf(med.z + b.z, 0.0f), fmaxf(med.w + b.w, 0.0f));
    ((float4*)g_h1)[(size_t)n * (D_HID / 4) + d4] = r;
}

// ---------------------------------------------------------------------------
// Layer-2 median + bias: 8 nodes/block, 16 threads/node, 4 feat/thread.
// ---------------------------------------------------------------------------
__global__ __launch_bounds__(128, 1)
void median_f4_out(const int* __restrict__ nb, const float* __restrict__ bias,
                   float* __restrict__ out) {
    const int local = threadIdx.x >> 4;               // 0..7
    const int n  = blockIdx.x * 8 + local;
    const int d4 = threadIdx.x & 15;

    __shared__ int sidx[8 * K_NB];
    if (threadIdx.x < 128)
        sidx[threadIdx.x] = nb[(size_t)(blockIdx.x * 8) * K_NB + threadIdx.x];
    if (threadIdx.x < 8 * K_NB - 128)
        sidx[128 + threadIdx.x] = nb[(size_t)(blockIdx.x * 8) * K_NB + 128 + threadIdx.x];
    __syncthreads();

    const float4* gp = (const float4*)g_g;
    float4 v[K_NB];
#pragma unroll
    for (int k = 0; k < K_NB; ++k)
        v[k] = __ldg(&gp[(size_t)sidx[local * K_NB + k] * (D_OUT / 4) + d4]);

    float4 med = median32_f4(v);
    float4 b = ((const float4*)bias)[d4];
    ((float4*)out)[(size_t)n * (D_OUT / 4) + d4] =
        make_float4(med.x + b.x, med.y + b.y, med.z + b.z, med.w + b.w);
}

// ---------------------------------------------------------------------------
extern "C" void kernel_launch(void* const* d_in, const int* in_sizes, int n_in,
                              void* d_out, int out_size) {
    const float* feat = (const float*)d_in[0];
    const float* W1   = (const float*)d_in[1];
    const float* b1   = (const float*)d_in[2];
    const float* W2   = (const float*)d_in[3];
    const float* b2   = (const float*)d_in[4];
    const int*   nb   = (const int*)d_in[5];
    float* out = (float*)d_out;

    void *ph = nullptr, *ph1 = nullptr, *pg = nullptr;
    cudaGetSymbolAddress(&ph,  g_h);
    cudaGetSymbolAddress(&ph1, g_h1);
    cudaGetSymbolAddress(&pg,  g_g);
    float* h  = (float*)ph;
    float* h1 = (float*)ph1;
    float* g  = (float*)pg;

    // 1) h = feat @ W1   [50000,512]x[512,128]  (bf16-split wmma, 2 CTA/SM)
    {
        dim3 grid(D_HID / 64, M_PAD / 128);
        gemm_bf16s<D_HID, D_IN><<<grid, 256>>>(feat, W1, h, N_NODES);
    }

    // 2) h1 = relu(median_k h[nb] + b1)   (float4 lanes)
    median_relu_f4<<<N_NODES / 4, 128>>>(nb, b1);

    // 3) g = h1 @ W2   [50048,128]x[128,64]  (bf16-split wmma)
    {
        dim3 grid(D_OUT / 64, M_PAD / 128);
        gemm_bf16s<D_OUT, D_HID><<<grid, 256>>>(h1, W2, g, M_PAD);
    }

    // 4) out = median_k g[nb] + b2   (float4 lanes)
    median_f4_out<<<N_NODES / 8, 128>>>(nb, b2, out);
}